// round 15
// baseline (speedup 1.0000x reference)
#include <cuda_runtime.h>
#include <cuda_bf16.h>

// ---------------------------------------------------------------------------
// SCN phase-merged: all 3 ranks per launch. Per rank r: L (NxN), x (Nx64),
// W (2x64x64):  dinv_i = rsqrt(sum_j |L_ij|); 2 layers of
// relu(dinv_i * L @ (dinv .* (x@W))); segment-sum pool (B=64); readout.
// Big GEMM bf16 tensor cores (m16n8k16), 3-stage BK=64 cp.async, split-K.
// ---------------------------------------------------------------------------

#define NMAX   8192
#define CCH    64
#define BSEG   64
#define OUTC   32
#define SPLIT_ELEMS 2097152            // S*N*64: 4*8192*64 == 8*4096*64

__device__ float g_dinv[3 * NMAX];
__device__ float g_part[3][SPLIT_ELEMS];
__device__ float g_pp[3 * 32 * BSEG * CCH];
__device__ __align__(16) __nv_bfloat16 g_Lbf[100663296];   // 4096^2+8192^2+4096^2
__device__ __align__(16) __nv_bfloat16 g_ut[3][64 * NMAX]; // U transposed [c][j]

struct RankP {
    const float* L; const float* x; const float* W0; const float* W1;
    const int* bel;
    float* dinv; __nv_bfloat16* Lbf; __nv_bfloat16* ut; float* P; float* pp;
    int N; int S;
};
struct AllP { RankP r[3]; };

__device__ __forceinline__ int rank_of(int b, int s1, int s2, int& local) {
    int ri = (b >= s1) + (b >= s2);
    local = b - (ri == 0 ? 0 : (ri == 1 ? s1 : s2));
    return ri;
}

__device__ __forceinline__ unsigned packbf(float a, float b) {
    __nv_bfloat162 p = __float22bfloat162_rn(make_float2(a, b));
    return *(unsigned*)&p;
}

// ---------------- phase 1: rowsum -> dinv, and L -> bf16 copy --------------
__global__ void scn_rowsum_all(AllP p, int s1, int s2) {
    int local;
    const RankP rp = p.r[rank_of(blockIdx.x, s1, s2, local)];
    int N = rp.N, row = local;
    const float4* Lr = (const float4*)(rp.L + (long)row * N);
    uint2* Wout = (uint2*)(rp.Lbf + (long)row * N);
    int n4 = N >> 2;
    float s = 0.f;
    for (int j = threadIdx.x; j < n4; j += blockDim.x) {
        float4 v = Lr[j];
        s += fabsf(v.x) + fabsf(v.y) + fabsf(v.z) + fabsf(v.w);
        __nv_bfloat162 p0 = __float22bfloat162_rn(make_float2(v.x, v.y));
        __nv_bfloat162 p1 = __float22bfloat162_rn(make_float2(v.z, v.w));
        Wout[j] = make_uint2(*(unsigned*)&p0, *(unsigned*)&p1);
    }
#pragma unroll
    for (int o = 16; o > 0; o >>= 1) s += __shfl_down_sync(0xffffffffu, s, o);
    __shared__ float red[8];
    int lane = threadIdx.x & 31, w = threadIdx.x >> 5;
    if (lane == 0) red[w] = s;
    __syncthreads();
    if (threadIdx.x < 8) {
        s = red[threadIdx.x];
#pragma unroll
        for (int o = 4; o > 0; o >>= 1) s += __shfl_down_sync(0xffu, s, o);
        if (threadIdx.x == 0) rp.dinv[row] = (s > 0.f) ? rsqrtf(s) : 0.f;
    }
}

// ---------------- phase 2: Ut[c][j] = bf16(dinv_j * (x @ W0)_jc) -----------
__global__ void scn_xw_all(AllP p, int s1, int s2) {
    __shared__ float Ws[64][64];
    __shared__ float Xs[32][64];
    int local;
    const RankP rp = p.r[rank_of(blockIdx.x, s1, s2, local)];
    int N = rp.N;
    int t = threadIdx.x;
    int r0 = local * 32;
#pragma unroll
    for (int j = 0; j < 4; j++)
        ((float4*)Ws)[t + 256 * j] = ((const float4*)rp.W0)[t + 256 * j];
#pragma unroll
    for (int j = 0; j < 2; j++)
        ((float4*)Xs)[t + 256 * j] = ((const float4*)(rp.x + (long)r0 * 64))[t + 256 * j];
    __syncthreads();
    int c = t & 63, g = t >> 6;
    float acc[8] = {0.f, 0.f, 0.f, 0.f, 0.f, 0.f, 0.f, 0.f};
#pragma unroll 16
    for (int k = 0; k < 64; k++) {
        float w = Ws[k][c];
#pragma unroll
        for (int r = 0; r < 8; r++)
            acc[r] = fmaf(Xs[g * 8 + r][k], w, acc[r]);
    }
    uint4 wv;
    unsigned* wp = (unsigned*)&wv;
#pragma unroll
    for (int q = 0; q < 4; q++) {
        int row = r0 + g * 8 + q * 2;
        wp[q] = packbf(rp.dinv[row] * acc[q * 2], rp.dinv[row + 1] * acc[q * 2 + 1]);
    }
    *(uint4*)(rp.ut + (long)c * N + r0 + g * 8) = wv;
}

// ---------------- GEMM phase: bf16 split-K, 3-stage BK=64 ------------------
#define LS_B 18432        // 128 rows * 72 bf16 * 2B
#define US_B 9216         // 64 rows * 72 bf16 * 2B
#define ROWW 36           // 72 bf16 = 36 u32 words per row
#define GSTAGES 3
#define GEMM_SMEM (GSTAGES * (LS_B + US_B))   // 82944

__device__ __forceinline__ void cpa16(unsigned smaddr, const void* g) {
    asm volatile("cp.async.cg.shared.global [%0], [%1], 16;" :: "r"(smaddr), "l"(g));
}

__global__ __launch_bounds__(256, 2)
void scn_gemm_all(AllP p, int s1, int s2) {
    extern __shared__ char smem[];
    unsigned sbase = (unsigned)__cvta_generic_to_shared(smem);
    const unsigned* SW = (const unsigned*)smem;
    unsigned us_base = sbase + (unsigned)GSTAGES * LS_B;

    int local;
    const RankP rp = p.r[rank_of(blockIdx.x, s1, s2, local)];
    int N = rp.N;
    int kChunk = N / rp.S;
    int mT = N >> 7;
    int bx = local % mT, by = local / mT;
    const __nv_bfloat16* __restrict__ L = rp.Lbf;
    const __nv_bfloat16* __restrict__ Ut = rp.ut;

    int t = threadIdx.x;
    int wid = t >> 5, lane = t & 31;
    int g = lane >> 2, tq = lane & 3;
    int warp_m = wid & 3, warp_n = wid >> 2;          // 4 x 2 warp grid
    int m0 = bx * 128;
    long kbase = (long)by * kChunk;
    int iters = kChunk / 64;

    int l_row[4], l_ch[4], u_row[2], u_ch[2];
#pragma unroll
    for (int j = 0; j < 4; j++) { int f = t + 256 * j; l_row[j] = f >> 3; l_ch[j] = f & 7; }
#pragma unroll
    for (int j = 0; j < 2; j++) { int f = t + 256 * j; u_row[j] = f >> 3; u_ch[j] = f & 7; }

    float acc[2][4][4];
#pragma unroll
    for (int mi = 0; mi < 2; mi++)
#pragma unroll
        for (int ni = 0; ni < 4; ni++)
#pragma unroll
            for (int q = 0; q < 4; q++) acc[mi][ni][q] = 0.f;

#define ISSUE_TILE(IT, BUF)                                                            \
    do {                                                                               \
        long k0_ = kbase + (long)(IT) * 64;                                            \
        _Pragma("unroll")                                                              \
        for (int j = 0; j < 4; j++)                                                    \
            cpa16(sbase + (BUF) * LS_B + l_row[j] * 144 + l_ch[j] * 16,                \
                  L + (long)(m0 + l_row[j]) * N + k0_ + l_ch[j] * 8);                  \
        _Pragma("unroll")                                                              \
        for (int j = 0; j < 2; j++)                                                    \
            cpa16(us_base + (BUF) * US_B + u_row[j] * 144 + u_ch[j] * 16,              \
                  Ut + (long)u_row[j] * N + k0_ + u_ch[j] * 8);                        \
        asm volatile("cp.async.commit_group;");                                        \
    } while (0)

    ISSUE_TILE(0, 0);
    ISSUE_TILE(1, 1);

    int buf = 0;
    for (int it = 0; it < iters; it++) {
        if (it + 2 < iters) {
            int nb = buf + 2; if (nb >= GSTAGES) nb -= GSTAGES;
            ISSUE_TILE(it + 2, nb);
            asm volatile("cp.async.wait_group 2;");
        } else {
            if (it + 2 == iters + 0 && it + 1 < iters)
                asm volatile("cp.async.wait_group 1;");
            else
                asm volatile("cp.async.wait_group 0;");
        }
        __syncthreads();

        const unsigned* Lw = SW + (buf * LS_B) / 4;
        const unsigned* Uw = SW + (GSTAGES * LS_B + buf * US_B) / 4;
#pragma unroll
        for (int kk = 0; kk < 4; kk++) {           // 4 x k16 steps
            int kw = kk * 8 + tq;
            unsigned a[2][4], b[4][2];
#pragma unroll
            for (int mi = 0; mi < 2; mi++) {
                int r = warp_m * 32 + mi * 16 + g;
                a[mi][0] = Lw[r * ROWW + kw];
                a[mi][1] = Lw[(r + 8) * ROWW + kw];
                a[mi][2] = Lw[r * ROWW + kw + 4];
                a[mi][3] = Lw[(r + 8) * ROWW + kw + 4];
            }
#pragma unroll
            for (int ni = 0; ni < 4; ni++) {
                int n = warp_n * 32 + ni * 8 + g;
                b[ni][0] = Uw[n * ROWW + kw];
                b[ni][1] = Uw[n * ROWW + kw + 4];
            }
#pragma unroll
            for (int mi = 0; mi < 2; mi++)
#pragma unroll
                for (int ni = 0; ni < 4; ni++)
                    asm volatile(
                        "mma.sync.aligned.m16n8k16.row.col.f32.bf16.bf16.f32 "
                        "{%0,%1,%2,%3}, {%4,%5,%6,%7}, {%8,%9}, {%0,%1,%2,%3};"
                        : "+f"(acc[mi][ni][0]), "+f"(acc[mi][ni][1]),
                          "+f"(acc[mi][ni][2]), "+f"(acc[mi][ni][3])
                        : "r"(a[mi][0]), "r"(a[mi][1]), "r"(a[mi][2]), "r"(a[mi][3]),
                          "r"(b[ni][0]), "r"(b[ni][1]));
        }
        __syncthreads();
        if (++buf == GSTAGES) buf = 0;
    }

    float* Pb = rp.P + (long)by * N * 64;
#pragma unroll
    for (int mi = 0; mi < 2; mi++) {
        int r = m0 + warp_m * 32 + mi * 16 + g;
#pragma unroll
        for (int ni = 0; ni < 4; ni++) {
            int c = warp_n * 32 + ni * 8 + 2 * tq;
            *(float2*)(Pb + (long)r * 64 + c)       = make_float2(acc[mi][ni][0], acc[mi][ni][1]);
            *(float2*)(Pb + (long)(r + 8) * 64 + c) = make_float2(acc[mi][ni][2], acc[mi][ni][3]);
        }
    }
}

// ------- phase: combine split-K + relu + layer-1 xW -> bf16 Ut -------------
template <int S>
__device__ __forceinline__ void combine_xw_body(const RankP& rp, int local) {
    __shared__ float Ws[64][64];
    __shared__ float Xs[32][64];
    int N = rp.N;
    const float* P = rp.P;
    int t = threadIdx.x;
    int r0 = local * 32;
#pragma unroll
    for (int j = 0; j < 4; j++)
        ((float4*)Ws)[t + 256 * j] = ((const float4*)rp.W1)[t + 256 * j];

    long stride4 = (long)N * 16;
#pragma unroll
    for (int j = 0; j < 2; j++) {
        int f = t + 256 * j;
        int lrow = f >> 4, c4 = f & 15;
        long base = (long)(r0 + lrow) * 16 + c4;
        float4 s = ((const float4*)P)[base];
#pragma unroll
        for (int q = 1; q < S; q++) {
            float4 v = ((const float4*)P)[(long)q * stride4 + base];
            s.x += v.x; s.y += v.y; s.z += v.z; s.w += v.w;
        }
        float d = rp.dinv[r0 + lrow];
        *(float4*)&Xs[lrow][c4 * 4] = make_float4(
            fmaxf(d * s.x, 0.f), fmaxf(d * s.y, 0.f),
            fmaxf(d * s.z, 0.f), fmaxf(d * s.w, 0.f));
    }
    __syncthreads();

    int c = t & 63, g = t >> 6;
    float acc[8] = {0.f, 0.f, 0.f, 0.f, 0.f, 0.f, 0.f, 0.f};
#pragma unroll 16
    for (int k = 0; k < 64; k++) {
        float w = Ws[k][c];
#pragma unroll
        for (int r = 0; r < 8; r++)
            acc[r] = fmaf(Xs[g * 8 + r][k], w, acc[r]);
    }
    uint4 wv;
    unsigned* wp = (unsigned*)&wv;
#pragma unroll
    for (int q = 0; q < 4; q++) {
        int row = r0 + g * 8 + q * 2;
        wp[q] = packbf(rp.dinv[row] * acc[q * 2], rp.dinv[row + 1] * acc[q * 2 + 1]);
    }
    *(uint4*)(rp.ut + (long)c * N + r0 + g * 8) = wv;
}

__global__ __launch_bounds__(256)
void scn_combine_xw_all(AllP p, int s1, int s2) {
    int local;
    const RankP rp = p.r[rank_of(blockIdx.x, s1, s2, local)];
    if (rp.S == 4) combine_xw_body<4>(rp, local);
    else           combine_xw_body<8>(rp, local);
}

// ------- phase: final combine + relu + deterministic segment pooling -------
template <int S>
__device__ __forceinline__ void combine_pool_body(const RankP& rp, int local, float* part) {
    int N = rp.N;
    const float* P = rp.P;
    int t = threadIdx.x;
    int c = t & 63, sg = t >> 6;                 // subgroup 0..3
    for (int i = t; i < 4 * BSEG * CCH; i += 256) part[i] = 0.f;
    __syncthreads();
    float* my = part + sg * BSEG * CCH;
    long stride = (long)N * 64;
    int r0 = local * 256 + sg * 64;
    for (int i = 0; i < 64; i++) {               // fixed order -> deterministic
        int row = r0 + i;
        long base = (long)row * 64 + c;
        float s = P[base];
#pragma unroll
        for (int q = 1; q < S; q++) s += P[(long)q * stride + base];
        float v = fmaxf(rp.dinv[row] * s, 0.f);
        my[rp.bel[row] * CCH + c] += v;
    }
    __syncthreads();
    float* out = rp.pp + (long)local * BSEG * CCH;
    for (int i = t; i < BSEG * CCH; i += 256)
        out[i] = ((part[i] + part[BSEG * CCH + i]) +
                  (part[2 * BSEG * CCH + i] + part[3 * BSEG * CCH + i]));
}

__global__ __launch_bounds__(256)
void scn_combine_pool_all(AllP p, int s1, int s2) {
    extern __shared__ float part[];              // [4][64][64]
    int local;
    const RankP rp = p.r[rank_of(blockIdx.x, s1, s2, local)];
    if (rp.S == 4) combine_pool_body<4>(rp, local, part);
    else           combine_pool_body<8>(rp, local, part);
}

// ------- fused pool-reduce + readout: one block per batch segment b --------
__global__ __launch_bounds__(128)
void scn_readout_fused(const float* __restrict__ PP,
                       const float* __restrict__ Wr0, const float* __restrict__ br0,
                       const float* __restrict__ Wr1, const float* __restrict__ br1,
                       const float* __restrict__ Wr2, const float* __restrict__ br2,
                       int G0, int G1, int G2, float* __restrict__ out) {
    __shared__ float pooled[3][64];
    int b = blockIdx.x;          // 0..63
    int t = threadIdx.x;         // 128 threads
    if (t < 64) {
        int Gs[3] = {G0, G1, G2};
#pragma unroll
        for (int r = 0; r < 3; r++) {
            const float* base = PP + (long)r * 32 * BSEG * CCH + b * 64 + t;
            int G = Gs[r];
            float s = 0.f;
            for (int g = 0; g < G; g++) s += base[(long)g * BSEG * CCH];
            pooled[r][t] = s;
        }
    }
    __syncthreads();
    if (t < OUTC) {
        float s = br0[t] + br1[t] + br2[t];
#pragma unroll 8
        for (int c = 0; c < 64; c++) {
            s = fmaf(pooled[0][c], Wr0[c * 32 + t], s);
            s = fmaf(pooled[1][c], Wr1[c * 32 + t], s);
            s = fmaf(pooled[2][c], Wr2[c * 32 + t], s);
        }
        out[b * OUTC + t] = s;
    }
}

// ---------------------------------------------------------------------------
static void* symAddr(const void* sym) {
    void* p = nullptr;
    cudaGetSymbolAddress(&p, sym);
    return p;
}

extern "C" void kernel_launch(void* const* d_in, const int* in_sizes, int n_in,
                              void* d_out, int out_size) {
    const float *x[3], *L[3], *W[3], *Wr[3], *br[3];
    const int* bel[3];

    if (in_sizes[0] == 16777216) {                       // alpha order
        for (int r = 0; r < 3; r++) {
            L[r]  = (const float*)d_in[0 + r];
            W[r]  = (const float*)d_in[3 + r];
            Wr[r] = (const float*)d_in[6 + r];
            bel[r]= (const int*)  d_in[9 + r];
            br[r] = (const float*)d_in[12 + r];
            x[r]  = (const float*)d_in[15 + r];
        }
    } else if (in_sizes[9] == 8192) {                    // dict order
        for (int r = 0; r < 3; r++) {
            x[r]  = (const float*)d_in[0 + r];
            L[r]  = (const float*)d_in[3 + r];
            bel[r]= (const int*)  d_in[6 + r];
            W[r]  = (const float*)d_in[9 + r];
        }
        Wr[0] = (const float*)d_in[12]; br[0] = (const float*)d_in[13];
        Wr[1] = (const float*)d_in[14]; br[1] = (const float*)d_in[15];
        Wr[2] = (const float*)d_in[16]; br[2] = (const float*)d_in[17];
    } else {                                             // signature order
        for (int r = 0; r < 3; r++) {
            x[r]  = (const float*)d_in[0 + r];
            L[r]  = (const float*)d_in[3 + r];
            W[r]  = (const float*)d_in[6 + r];
            bel[r]= (const int*)  d_in[15 + r];
        }
        Wr[0] = (const float*)d_in[9];  br[0] = (const float*)d_in[10];
        Wr[1] = (const float*)d_in[11]; br[1] = (const float*)d_in[12];
        Wr[2] = (const float*)d_in[13]; br[2] = (const float*)d_in[14];
    }

    int Ns[3];
    if (in_sizes[0] == 16777216) {
        Ns[0] = in_sizes[15] / 64; Ns[1] = in_sizes[16] / 64; Ns[2] = in_sizes[17] / 64;
    } else {
        Ns[0] = in_sizes[0] / 64;  Ns[1] = in_sizes[1] / 64;  Ns[2] = in_sizes[2] / 64;
    }

    float* dinvAll = (float*)symAddr(g_dinv);
    float* part    = (float*)symAddr(g_part);
    float* pp      = (float*)symAddr(g_pp);
    __nv_bfloat16* LbfAll = (__nv_bfloat16*)symAddr(g_Lbf);
    __nv_bfloat16* utAll  = (__nv_bfloat16*)symAddr(g_ut);
    float* out     = (float*)d_out;

    long lbfOff[3];
    lbfOff[0] = 0;
    lbfOff[1] = lbfOff[0] + (long)Ns[0] * Ns[0];
    lbfOff[2] = lbfOff[1] + (long)Ns[1] * Ns[1];

    cudaFuncSetAttribute(scn_gemm_all, cudaFuncAttributeMaxDynamicSharedMemorySize, GEMM_SMEM);
    cudaFuncSetAttribute(scn_combine_pool_all, cudaFuncAttributeMaxDynamicSharedMemorySize, 65536);

    // Build per-rank params; ordering {1, 0, 2} puts the big rank's blocks first.
    AllP p;
    int order[3] = {1, 0, 2};
    for (int e = 0; e < 3; e++) {
        int r = order[e];
        RankP& q = p.r[e];
        q.L = L[r]; q.x = x[r]; q.W0 = W[r]; q.W1 = W[r] + 64 * 64; q.bel = bel[r];
        q.dinv = dinvAll + r * NMAX;
        q.Lbf = LbfAll + lbfOff[r];
        q.ut  = utAll + (long)r * 64 * NMAX;
        q.P   = part + (long)r * SPLIT_ELEMS;
        q.pp  = pp + (long)r * 32 * BSEG * CCH;
        q.N = Ns[r];
        q.S = (Ns[r] >= 8192) ? 4 : 8;
    }
    int N_a = p.r[0].N, N_b = p.r[1].N, N_c = p.r[2].N;

    // Phase grids (cumulative starts s1, s2)
    int rs1 = N_a,        rs2 = N_a + N_b,        rTot = N_a + N_b + N_c;
    int xs1 = N_a / 32,   xs2 = (N_a + N_b) / 32, xTot = rTot / 32;
    int g_a = (N_a / 128) * p.r[0].S, g_b = (N_b / 128) * p.r[1].S, g_c = (N_c / 128) * p.r[2].S;
    int gs1 = g_a, gs2 = g_a + g_b, gTot = g_a + g_b + g_c;
    int ps1 = N_a / 256, ps2 = (N_a + N_b) / 256, pTot = rTot / 256;

    // Phase-merged single-stream schedule (graph-capturable)
    scn_rowsum_all<<<rTot, 256>>>(p, rs1, rs2);
    scn_xw_all<<<xTot, 256>>>(p, xs1, xs2);
    scn_gemm_all<<<gTot, 256, GEMM_SMEM>>>(p, gs1, gs2);
    scn_combine_xw_all<<<xTot, 256>>>(p, xs1, xs2);
    scn_gemm_all<<<gTot, 256, GEMM_SMEM>>>(p, gs1, gs2);
    scn_combine_pool_all<<<pTot, 256, 65536>>>(p, ps1, ps2);
    scn_readout_fused<<<BSEG, 128>>>(pp, Wr[0], br[0], Wr[1], br[1], Wr[2], br[2],
                                     Ns[0] / 256, Ns[1] / 256, Ns[2] / 256, out);
}

// round 16
// speedup vs baseline: 1.2893x; 1.2893x over previous
#include <cuda_runtime.h>
#include <cuda_bf16.h>

// ---------------------------------------------------------------------------
// SCN: per rank r with L (N x N), x (N x 64), W (2 x 64 x 64):
//   dinv_i = rsqrt(sum_j |L_ij|)  (0 if sum==0)
//   layer:  x = relu( dinv_i * sum_j L_ij * (dinv_j * (x @ W[layer])_j) )
//   pooled[b] = sum_{i: bel_i==b} x_i   (B=64);  out += pooled @ Wr + br
// Big GEMM on bf16 tensor cores (m16n8k16); rowsum converts L->bf16 once;
// U kept transposed bf16. 3-stage BK=64 cp.async GEMM, split-K S=4 (N=8192)
// or S=8 (N=4096); fused combine+xw / combine+pool / reduce+readout.
// 3 per-rank streams, rank-1 (big) stream at high priority.
// ---------------------------------------------------------------------------

#define NMAX   8192
#define CCH    64
#define BSEG   64
#define OUTC   32
#define SPLIT_ELEMS 2097152            // S*N*64: 4*8192*64 == 8*4096*64

__device__ float g_dinv[3 * NMAX];
__device__ float g_part[3][SPLIT_ELEMS];
__device__ float g_pp[3 * 32 * BSEG * CCH];
__device__ __align__(16) __nv_bfloat16 g_Lbf[100663296];   // 4096^2+8192^2+4096^2
__device__ __align__(16) __nv_bfloat16 g_ut[3][64 * NMAX]; // U transposed [c][j]

// ---------------- rowsum -> dinv, and L -> bf16 copy ----------------
__global__ void scn_rowsum(const float* __restrict__ L, float* __restrict__ dinv,
                           __nv_bfloat16* __restrict__ L16, int N) {
    int row = blockIdx.x;
    const float4* Lr = (const float4*)(L + (long)row * N);
    uint2* Wout = (uint2*)(L16 + (long)row * N);
    int n4 = N >> 2;
    float s = 0.f;
    for (int j = threadIdx.x; j < n4; j += blockDim.x) {
        float4 v = Lr[j];
        s += fabsf(v.x) + fabsf(v.y) + fabsf(v.z) + fabsf(v.w);
        __nv_bfloat162 p0 = __float22bfloat162_rn(make_float2(v.x, v.y));
        __nv_bfloat162 p1 = __float22bfloat162_rn(make_float2(v.z, v.w));
        Wout[j] = make_uint2(*(unsigned*)&p0, *(unsigned*)&p1);
    }
#pragma unroll
    for (int o = 16; o > 0; o >>= 1) s += __shfl_down_sync(0xffffffffu, s, o);
    __shared__ float red[8];
    int lane = threadIdx.x & 31, w = threadIdx.x >> 5;
    if (lane == 0) red[w] = s;
    __syncthreads();
    if (threadIdx.x < 8) {
        s = red[threadIdx.x];
#pragma unroll
        for (int o = 4; o > 0; o >>= 1) s += __shfl_down_sync(0xffu, s, o);
        if (threadIdx.x == 0) dinv[row] = (s > 0.f) ? rsqrtf(s) : 0.f;
    }
}

__device__ __forceinline__ unsigned packbf(float a, float b) {
    __nv_bfloat162 p = __float22bfloat162_rn(make_float2(a, b));
    return *(unsigned*)&p;
}

// ---------------- Ut[c][j] = bf16( dinv_j * (x @ W)_jc )  (layer 0) --------
__global__ void scn_xw(const float* __restrict__ X, const float* __restrict__ W,
                       const float* __restrict__ dinv, __nv_bfloat16* __restrict__ Ut,
                       int N) {
    __shared__ float Ws[64][64];
    __shared__ float Xs[32][64];
    int t = threadIdx.x;
    int r0 = blockIdx.x * 32;
#pragma unroll
    for (int j = 0; j < 4; j++)
        ((float4*)Ws)[t + 256 * j] = ((const float4*)W)[t + 256 * j];
#pragma unroll
    for (int j = 0; j < 2; j++)
        ((float4*)Xs)[t + 256 * j] = ((const float4*)(X + (long)r0 * 64))[t + 256 * j];
    __syncthreads();
    int c = t & 63, g = t >> 6;
    float acc[8] = {0.f, 0.f, 0.f, 0.f, 0.f, 0.f, 0.f, 0.f};
#pragma unroll 16
    for (int k = 0; k < 64; k++) {
        float w = Ws[k][c];
#pragma unroll
        for (int r = 0; r < 8; r++)
            acc[r] = fmaf(Xs[g * 8 + r][k], w, acc[r]);
    }
    uint4 wv;
    unsigned* wp = (unsigned*)&wv;
#pragma unroll
    for (int p = 0; p < 4; p++) {
        int row = r0 + g * 8 + p * 2;
        wp[p] = packbf(dinv[row] * acc[p * 2], dinv[row + 1] * acc[p * 2 + 1]);
    }
    *(uint4*)(Ut + (long)c * N + r0 + g * 8) = wv;
}

// ---------------- bf16 tensor-core split-K GEMM, 3-stage BK=64 -------------
#define LS_B 18432        // 128 rows * 72 bf16 * 2B
#define US_B 9216         // 64 rows * 72 bf16 * 2B
#define ROWW 36           // 72 bf16 = 36 u32 words per row
#define GSTAGES 3
#define GEMM_SMEM (GSTAGES * (LS_B + US_B))   // 82944

__device__ __forceinline__ void cpa16(unsigned smaddr, const void* g) {
    asm volatile("cp.async.cg.shared.global [%0], [%1], 16;" :: "r"(smaddr), "l"(g));
}

__global__ __launch_bounds__(256, 2)
void scn_gemm_bf16(const __nv_bfloat16* __restrict__ L, const __nv_bfloat16* __restrict__ Ut,
                   float* __restrict__ P, int N, int kChunk) {
    extern __shared__ char smem[];
    unsigned sbase = (unsigned)__cvta_generic_to_shared(smem);
    const unsigned* SW = (const unsigned*)smem;
    unsigned us_base = sbase + (unsigned)GSTAGES * LS_B;

    int t = threadIdx.x;
    int wid = t >> 5, lane = t & 31;
    int g = lane >> 2, tq = lane & 3;
    int warp_m = wid & 3, warp_n = wid >> 2;          // 4 x 2 warp grid
    int m0 = blockIdx.x * 128;
    long kbase = (long)blockIdx.y * kChunk;
    int iters = kChunk / 64;

    int l_row[4], l_ch[4], u_row[2], u_ch[2];
#pragma unroll
    for (int j = 0; j < 4; j++) { int f = t + 256 * j; l_row[j] = f >> 3; l_ch[j] = f & 7; }
#pragma unroll
    for (int j = 0; j < 2; j++) { int f = t + 256 * j; u_row[j] = f >> 3; u_ch[j] = f & 7; }

    float acc[2][4][4];
#pragma unroll
    for (int mi = 0; mi < 2; mi++)
#pragma unroll
        for (int ni = 0; ni < 4; ni++)
#pragma unroll
            for (int q = 0; q < 4; q++) acc[mi][ni][q] = 0.f;

#define ISSUE_TILE(IT, BUF)                                                            \
    do {                                                                               \
        long k0_ = kbase + (long)(IT) * 64;                                            \
        _Pragma("unroll")                                                              \
        for (int j = 0; j < 4; j++)                                                    \
            cpa16(sbase + (BUF) * LS_B + l_row[j] * 144 + l_ch[j] * 16,                \
                  L + (long)(m0 + l_row[j]) * N + k0_ + l_ch[j] * 8);                  \
        _Pragma("unroll")                                                              \
        for (int j = 0; j < 2; j++)                                                    \
            cpa16(us_base + (BUF) * US_B + u_row[j] * 144 + u_ch[j] * 16,              \
                  Ut + (long)u_row[j] * N + k0_ + u_ch[j] * 8);                        \
        asm volatile("cp.async.commit_group;");                                        \
    } while (0)

    ISSUE_TILE(0, 0);
    ISSUE_TILE(1, 1);

    int buf = 0;
    for (int it = 0; it < iters; it++) {
        if (it + 2 < iters) {
            int nb = buf + 2; if (nb >= GSTAGES) nb -= GSTAGES;
            ISSUE_TILE(it + 2, nb);
            asm volatile("cp.async.wait_group 2;");
        } else {
            if (it + 2 == iters + 0 && it + 1 < iters)
                asm volatile("cp.async.wait_group 1;");
            else
                asm volatile("cp.async.wait_group 0;");
        }
        __syncthreads();

        const unsigned* Lw = SW + (buf * LS_B) / 4;
        const unsigned* Uw = SW + (GSTAGES * LS_B + buf * US_B) / 4;
#pragma unroll
        for (int kk = 0; kk < 4; kk++) {           // 4 x k16 steps
            int kw = kk * 8 + tq;
            unsigned a[2][4], b[4][2];
#pragma unroll
            for (int mi = 0; mi < 2; mi++) {
                int r = warp_m * 32 + mi * 16 + g;
                a[mi][0] = Lw[r * ROWW + kw];
                a[mi][1] = Lw[(r + 8) * ROWW + kw];
                a[mi][2] = Lw[r * ROWW + kw + 4];
                a[mi][3] = Lw[(r + 8) * ROWW + kw + 4];
            }
#pragma unroll
            for (int ni = 0; ni < 4; ni++) {
                int n = warp_n * 32 + ni * 8 + g;
                b[ni][0] = Uw[n * ROWW + kw];
                b[ni][1] = Uw[n * ROWW + kw + 4];
            }
#pragma unroll
            for (int mi = 0; mi < 2; mi++)
#pragma unroll
                for (int ni = 0; ni < 4; ni++)
                    asm volatile(
                        "mma.sync.aligned.m16n8k16.row.col.f32.bf16.bf16.f32 "
                        "{%0,%1,%2,%3}, {%4,%5,%6,%7}, {%8,%9}, {%0,%1,%2,%3};"
                        : "+f"(acc[mi][ni][0]), "+f"(acc[mi][ni][1]),
                          "+f"(acc[mi][ni][2]), "+f"(acc[mi][ni][3])
                        : "r"(a[mi][0]), "r"(a[mi][1]), "r"(a[mi][2]), "r"(a[mi][3]),
                          "r"(b[ni][0]), "r"(b[ni][1]));
        }
        __syncthreads();
        if (++buf == GSTAGES) buf = 0;
    }

    float* Pb = P + (long)blockIdx.y * N * 64;
#pragma unroll
    for (int mi = 0; mi < 2; mi++) {
        int r = m0 + warp_m * 32 + mi * 16 + g;
#pragma unroll
        for (int ni = 0; ni < 4; ni++) {
            int c = warp_n * 32 + ni * 8 + 2 * tq;
            *(float2*)(Pb + (long)r * 64 + c)       = make_float2(acc[mi][ni][0], acc[mi][ni][1]);
            *(float2*)(Pb + (long)(r + 8) * 64 + c) = make_float2(acc[mi][ni][2], acc[mi][ni][3]);
        }
    }
}

// ------- fused: combine split-K + relu + layer-1 xW -> transposed bf16 Ut --
template <int S>
__global__ __launch_bounds__(256)
void scn_combine_xw(const float* __restrict__ P, const float* __restrict__ dinv,
                    const float* __restrict__ W, __nv_bfloat16* __restrict__ Ut, int N) {
    __shared__ float Ws[64][64];
    __shared__ float Xs[32][64];
    int t = threadIdx.x;
    int r0 = blockIdx.x * 32;
#pragma unroll
    for (int j = 0; j < 4; j++)
        ((float4*)Ws)[t + 256 * j] = ((const float4*)W)[t + 256 * j];

    long stride4 = (long)N * 16;
#pragma unroll
    for (int j = 0; j < 2; j++) {
        int f = t + 256 * j;
        int lrow = f >> 4, c4 = f & 15;
        long base = (long)(r0 + lrow) * 16 + c4;
        float4 s = ((const float4*)P)[base];
#pragma unroll
        for (int q = 1; q < S; q++) {
            float4 v = ((const float4*)P)[(long)q * stride4 + base];
            s.x += v.x; s.y += v.y; s.z += v.z; s.w += v.w;
        }
        float d = dinv[r0 + lrow];
        *(float4*)&Xs[lrow][c4 * 4] = make_float4(
            fmaxf(d * s.x, 0.f), fmaxf(d * s.y, 0.f),
            fmaxf(d * s.z, 0.f), fmaxf(d * s.w, 0.f));
    }
    __syncthreads();

    int c = t & 63, g = t >> 6;
    float acc[8] = {0.f, 0.f, 0.f, 0.f, 0.f, 0.f, 0.f, 0.f};
#pragma unroll 16
    for (int k = 0; k < 64; k++) {
        float w = Ws[k][c];
#pragma unroll
        for (int r = 0; r < 8; r++)
            acc[r] = fmaf(Xs[g * 8 + r][k], w, acc[r]);
    }
    uint4 wv;
    unsigned* wp = (unsigned*)&wv;
#pragma unroll
    for (int p = 0; p < 4; p++) {
        int row = r0 + g * 8 + p * 2;
        wp[p] = packbf(dinv[row] * acc[p * 2], dinv[row + 1] * acc[p * 2 + 1]);
    }
    *(uint4*)(Ut + (long)c * N + r0 + g * 8) = wv;
}

// ------- fused: final combine + relu + deterministic segment pooling -------
// grid = N/256, 256 threads = 4 subgroups x 64 columns, 64KB dynamic smem.
template <int S>
__global__ __launch_bounds__(256)
void scn_combine_pool(const float* __restrict__ P, const float* __restrict__ dinv,
                      const int* __restrict__ bel, float* __restrict__ PP, int N) {
    extern __shared__ float part[];              // [4][64][64]
    int t = threadIdx.x;
    int c = t & 63, sg = t >> 6;                 // subgroup 0..3
    for (int i = t; i < 4 * BSEG * CCH; i += 256) part[i] = 0.f;
    __syncthreads();
    float* my = part + sg * BSEG * CCH;
    long stride = (long)N * 64;
    int r0 = blockIdx.x * 256 + sg * 64;
    for (int i = 0; i < 64; i++) {               // fixed order -> deterministic
        int row = r0 + i;
        long base = (long)row * 64 + c;
        float s = P[base];
#pragma unroll
        for (int q = 1; q < S; q++) s += P[(long)q * stride + base];
        float v = fmaxf(dinv[row] * s, 0.f);
        my[bel[row] * CCH + c] += v;
    }
    __syncthreads();
    float* out = PP + (long)blockIdx.x * BSEG * CCH;
    for (int i = t; i < BSEG * CCH; i += 256)
        out[i] = ((part[i] + part[BSEG * CCH + i]) +
                  (part[2 * BSEG * CCH + i] + part[3 * BSEG * CCH + i]));
}

// ------- fused pool-reduce + readout: one block per batch segment b --------
__global__ __launch_bounds__(128)
void scn_readout_fused(const float* __restrict__ PP,
                       const float* __restrict__ Wr0, const float* __restrict__ br0,
                       const float* __restrict__ Wr1, const float* __restrict__ br1,
                       const float* __restrict__ Wr2, const float* __restrict__ br2,
                       int G0, int G1, int G2, float* __restrict__ out) {
    __shared__ float pooled[3][64];
    int b = blockIdx.x;          // 0..63
    int t = threadIdx.x;         // 128 threads
    if (t < 64) {
        int Gs[3] = {G0, G1, G2};
#pragma unroll
        for (int r = 0; r < 3; r++) {
            const float* base = PP + (long)r * 32 * BSEG * CCH + b * 64 + t;
            int G = Gs[r];
            float s = 0.f;
            for (int g = 0; g < G; g++) s += base[(long)g * BSEG * CCH];
            pooled[r][t] = s;
        }
    }
    __syncthreads();
    if (t < OUTC) {
        float s = br0[t] + br1[t] + br2[t];
#pragma unroll 8
        for (int c = 0; c < 64; c++) {
            s = fmaf(pooled[0][c], Wr0[c * 32 + t], s);
            s = fmaf(pooled[1][c], Wr1[c * 32 + t], s);
            s = fmaf(pooled[2][c], Wr2[c * 32 + t], s);
        }
        out[b * OUTC + t] = s;
    }
}

// ---------------------------------------------------------------------------
static void* symAddr(const void* sym) {
    void* p = nullptr;
    cudaGetSymbolAddress(&p, sym);
    return p;
}

extern "C" void kernel_launch(void* const* d_in, const int* in_sizes, int n_in,
                              void* d_out, int out_size) {
    const float *x[3], *L[3], *W[3], *Wr[3], *br[3];
    const int* bel[3];

    if (in_sizes[0] == 16777216) {                       // alpha order
        for (int r = 0; r < 3; r++) {
            L[r]  = (const float*)d_in[0 + r];
            W[r]  = (const float*)d_in[3 + r];
            Wr[r] = (const float*)d_in[6 + r];
            bel[r]= (const int*)  d_in[9 + r];
            br[r] = (const float*)d_in[12 + r];
            x[r]  = (const float*)d_in[15 + r];
        }
    } else if (in_sizes[9] == 8192) {                    // dict order
        for (int r = 0; r < 3; r++) {
            x[r]  = (const float*)d_in[0 + r];
            L[r]  = (const float*)d_in[3 + r];
            bel[r]= (const int*)  d_in[6 + r];
            W[r]  = (const float*)d_in[9 + r];
        }
        Wr[0] = (const float*)d_in[12]; br[0] = (const float*)d_in[13];
        Wr[1] = (const float*)d_in[14]; br[1] = (const float*)d_in[15];
        Wr[2] = (const float*)d_in[16]; br[2] = (const float*)d_in[17];
    } else {                                             // signature order
        for (int r = 0; r < 3; r++) {
            x[r]  = (const float*)d_in[0 + r];
            L[r]  = (const float*)d_in[3 + r];
            W[r]  = (const float*)d_in[6 + r];
            bel[r]= (const int*)  d_in[15 + r];
        }
        Wr[0] = (const float*)d_in[9];  br[0] = (const float*)d_in[10];
        Wr[1] = (const float*)d_in[11]; br[1] = (const float*)d_in[12];
        Wr[2] = (const float*)d_in[13]; br[2] = (const float*)d_in[14];
    }

    int Ns[3];
    if (in_sizes[0] == 16777216) {
        Ns[0] = in_sizes[15] / 64; Ns[1] = in_sizes[16] / 64; Ns[2] = in_sizes[17] / 64;
    } else {
        Ns[0] = in_sizes[0] / 64;  Ns[1] = in_sizes[1] / 64;  Ns[2] = in_sizes[2] / 64;
    }

    float* dinvAll = (float*)symAddr(g_dinv);
    float* part    = (float*)symAddr(g_part);
    float* pp      = (float*)symAddr(g_pp);
    __nv_bfloat16* LbfAll = (__nv_bfloat16*)symAddr(g_Lbf);
    __nv_bfloat16* utAll  = (__nv_bfloat16*)symAddr(g_ut);
    float* out     = (float*)d_out;

    long lbfOff[3];
    lbfOff[0] = 0;
    lbfOff[1] = lbfOff[0] + (long)Ns[0] * Ns[0];
    lbfOff[2] = lbfOff[1] + (long)Ns[1] * Ns[1];

    cudaFuncSetAttribute(scn_gemm_bf16, cudaFuncAttributeMaxDynamicSharedMemorySize, GEMM_SMEM);
    cudaFuncSetAttribute(scn_combine_pool<4>, cudaFuncAttributeMaxDynamicSharedMemorySize, 65536);
    cudaFuncSetAttribute(scn_combine_pool<8>, cudaFuncAttributeMaxDynamicSharedMemorySize, 65536);

    // Fork three per-rank streams off the capture stream (stream 0).
    // The big rank (largest N) gets the highest priority and is issued first.
    int prLo = 0, prHi = 0;
    cudaDeviceGetStreamPriorityRange(&prLo, &prHi);   // prHi = highest (most negative)

    int orderIdx[3] = {0, 1, 2};
    // sort descending by N (3 elements, fixed net)
    if (Ns[orderIdx[0]] < Ns[orderIdx[1]]) { int tmp = orderIdx[0]; orderIdx[0] = orderIdx[1]; orderIdx[1] = tmp; }
    if (Ns[orderIdx[0]] < Ns[orderIdx[2]]) { int tmp = orderIdx[0]; orderIdx[0] = orderIdx[2]; orderIdx[2] = tmp; }
    if (Ns[orderIdx[1]] < Ns[orderIdx[2]]) { int tmp = orderIdx[1]; orderIdx[1] = orderIdx[2]; orderIdx[2] = tmp; }

    cudaStream_t st[3];
    cudaEvent_t root, ev[3];
    cudaEventCreateWithFlags(&root, cudaEventDisableTiming);
    cudaEventRecord(root, 0);
    for (int e = 0; e < 3; e++) {
        int pr = (e == 0) ? prHi : prLo;
        cudaStreamCreateWithPriority(&st[e], cudaStreamNonBlocking, pr);
        cudaEventCreateWithFlags(&ev[e], cudaEventDisableTiming);
        cudaStreamWaitEvent(st[e], root, 0);
    }

    for (int e = 0; e < 3; e++) {
        int r = orderIdx[e];
        int N = Ns[r];
        int S = (N >= 8192) ? 4 : 8;     // grid = (N/128)*S = 256 CTAs per GEMM
        int kChunk = N / S;
        float* dinv = dinvAll + r * NMAX;
        __nv_bfloat16* Lbf = LbfAll + lbfOff[r];
        __nv_bfloat16* ut  = utAll + (long)r * 64 * NMAX;
        float* pr_  = part + (long)r * SPLIT_ELEMS;
        cudaStream_t s = st[e];

        scn_rowsum<<<N, 256, 0, s>>>(L[r], dinv, Lbf, N);
        // layer 0
        scn_xw<<<N / 32, 256, 0, s>>>(x[r], W[r], dinv, ut, N);
        scn_gemm_bf16<<<dim3(N / 128, S), 256, GEMM_SMEM, s>>>(Lbf, ut, pr_, N, kChunk);
        // combine + relu + layer-1 xW fused
        if (S == 4)
            scn_combine_xw<4><<<N / 32, 256, 0, s>>>(pr_, dinv, W[r] + 64 * 64, ut, N);
        else
            scn_combine_xw<8><<<N / 32, 256, 0, s>>>(pr_, dinv, W[r] + 64 * 64, ut, N);
        // layer 1
        scn_gemm_bf16<<<dim3(N / 128, S), 256, GEMM_SMEM, s>>>(Lbf, ut, pr_, N, kChunk);
        // final combine + relu + pooling fused
        int G = N / 256;
        float* ppr = pp + (long)r * 32 * BSEG * CCH;
        if (S == 4)
            scn_combine_pool<4><<<G, 256, 65536, s>>>(pr_, dinv, bel[r], ppr, N);
        else
            scn_combine_pool<8><<<G, 256, 65536, s>>>(pr_, dinv, bel[r], ppr, N);
        cudaEventRecord(ev[e], s);
    }

    // Join back to the capture stream; fused reduce+readout.
    for (int e = 0; e < 3; e++) cudaStreamWaitEvent((cudaStream_t)0, ev[e], 0);
    scn_readout_fused<<<BSEG, 128>>>(pp, Wr[0], br[0], Wr[1], br[1], Wr[2], br[2],
                                     Ns[0] / 256, Ns[1] / 256, Ns[2] / 256, out);

    for (int e = 0; e < 3; e++) {
        cudaStreamDestroy(st[e]);
        cudaEventDestroy(ev[e]);
    }
    cudaEventDestroy(root);
}